// round 6
// baseline (speedup 1.0000x reference)
#include <cuda_runtime.h>
#include <cuda_bf16.h>
#include <math.h>
#include <stdint.h>

#define NB 2
#define SEQ 1024
#define NTOK (NB * SEQ)          // 2048
#define DEMB 1024
#define NHEAD 16
#define DH 64
#define DFF 4096
#define NVOCAB 32000
#define NLAYER 6

// -------- scratch (device globals; no allocation allowed) --------
__device__ float g_x [NTOK * DEMB];
__device__ float g_h1[NTOK * DEMB];
__device__ float g_h2[NTOK * DEMB];
__device__ float g_t [NTOK * DEMB];
__device__ float g_q [NTOK * DEMB];
__device__ float g_k [NTOK * DEMB];
__device__ float g_v [NTOK * DEMB];
__device__ float g_ff[NTOK * DFF];

// ---------------- split-bf16 helper: x = hi(bf16) + lo(bf16), hi exact-truncate ----------------
__device__ __forceinline__ void split2(float x0, float x1, uint32_t& hi, uint32_t& lo) {
    uint32_t u0 = __float_as_uint(x0), u1 = __float_as_uint(x1);
    hi = __byte_perm(u0, u1, 0x7632);                    // {bf16(x1), bf16(x0)} truncated
    float l0 = x0 - __uint_as_float(u0 & 0xffff0000u);   // exact
    float l1 = x1 - __uint_as_float(u1 & 0xffff0000u);
    asm("cvt.rn.bf16x2.f32 %0, %1, %2;" : "=r"(lo) : "f"(l1), "f"(l0));
}

#define MMA(acc, a0, a1, a2, a3, b0, b1)                                        \
    asm("mma.sync.aligned.m16n8k16.row.col.f32.bf16.bf16.f32 "                  \
        "{%0,%1,%2,%3}, {%4,%5,%6,%7}, {%8,%9}, {%0,%1,%2,%3};"                 \
        : "+f"((acc)[0]), "+f"((acc)[1]), "+f"((acc)[2]), "+f"((acc)[3])        \
        : "r"(a0), "r"(a1), "r"(a2), "r"(a3), "r"(b0), "r"(b1))

// ============ pipelined split-bf16 HMMA GEMM: C[M,N] = A[M,K]@B[K,N] + bias ============
// grid = (M/128, N/128) (x = m fastest so a wave shares B strips in L2), block = 256.
// Double-buffered SMEM + register prefetch; 2 CTAs/SM via launch bounds.
#define STRIDE 20
#define BUF_WORDS (4 * 128 * STRIDE)     // Ah, Al, Bh, Bl per buffer = 10240 words
#define GEMM_SMEM (2 * BUF_WORDS * 4)    // 81920 bytes

__global__ __launch_bounds__(256, 2) void gemm_hmma(const float* __restrict__ A,
                                                    const float* __restrict__ B,
                                                    const float* __restrict__ bias,
                                                    float* __restrict__ C,
                                                    int N, int K, int relu) {
    extern __shared__ uint32_t sh[];
    int tid = threadIdx.x, wid = tid >> 5, lane = tid & 31;
    int bm = blockIdx.x * 128, bn = blockIdx.y * 128;
    int wm = (wid >> 2) * 64, wn = (wid & 3) * 32;
    int r = lane >> 2, c = lane & 3;

    int ac4 = (tid & 7) * 4;             // A k-offset 0..28
    float4 ar[4];
    float2 br[8];

#define LOAD_REGS(k0)                                                            \
    {                                                                            \
        _Pragma("unroll")                                                        \
        for (int p = 0; p < 4; p++) {                                            \
            int row = (tid + p * 256) >> 3;                                      \
            ar[p] = *(const float4*)(A + (size_t)(bm + row) * K + (k0) + ac4);   \
        }                                                                        \
        _Pragma("unroll")                                                        \
        for (int p = 0; p < 8; p++) {                                            \
            int idx = tid + p * 256;                                             \
            int n = idx & 127, kp = idx >> 7;                                    \
            const float* bp = B + (size_t)((k0) + kp * 2) * N + bn + n;          \
            br[p] = make_float2(bp[0], bp[N]);                                   \
        }                                                                        \
    }

#define STORE_REGS(buf)                                                          \
    {                                                                            \
        uint32_t* Ah = sh + (buf) * BUF_WORDS;                                   \
        uint32_t* Al = Ah + 2560;                                                \
        uint32_t* Bh = Al + 2560;                                                \
        uint32_t* Bl = Bh + 2560;                                                \
        _Pragma("unroll")                                                        \
        for (int p = 0; p < 4; p++) {                                            \
            int row = (tid + p * 256) >> 3;                                      \
            uint32_t h0, l0, h1, l1;                                             \
            split2(ar[p].x, ar[p].y, h0, l0);                                    \
            split2(ar[p].z, ar[p].w, h1, l1);                                    \
            int o = row * STRIDE + (ac4 >> 1);                                   \
            Ah[o] = h0; Ah[o + 1] = h1;                                          \
            Al[o] = l0; Al[o + 1] = l1;                                          \
        }                                                                        \
        _Pragma("unroll")                                                        \
        for (int p = 0; p < 8; p++) {                                            \
            int idx = tid + p * 256;                                             \
            int n = idx & 127, kp = idx >> 7;                                    \
            uint32_t h, l;                                                       \
            split2(br[p].x, br[p].y, h, l);                                      \
            Bh[n * STRIDE + kp] = h;                                             \
            Bl[n * STRIDE + kp] = l;                                             \
        }                                                                        \
    }

    float acc[4][4][4] = {};

    LOAD_REGS(0);
    STORE_REGS(0);

    int KT = K >> 5;
    for (int kt = 0; kt < KT; kt++) {
        if (kt + 1 < KT) LOAD_REGS((kt + 1) << 5);     // prefetch overlaps compute
        __syncthreads();
        uint32_t* Ah = sh + (kt & 1) * BUF_WORDS;
        uint32_t* Al = Ah + 2560;
        uint32_t* Bh = Al + 2560;
        uint32_t* Bl = Bh + 2560;
#pragma unroll
        for (int s = 0; s < 2; s++) {
            uint32_t bh[4][2], bl[4][2];
#pragma unroll
            for (int j = 0; j < 4; j++) {
                int o = (wn + 8 * j + r) * STRIDE + s * 8 + c;
                bh[j][0] = Bh[o]; bh[j][1] = Bh[o + 4];
                bl[j][0] = Bl[o]; bl[j][1] = Bl[o + 4];
            }
#pragma unroll
            for (int i = 0; i < 4; i++) {
                int o0 = (wm + 16 * i + r) * STRIDE + s * 8 + c;
                int o1 = o0 + 8 * STRIDE;
                uint32_t ah0 = Ah[o0], ah1 = Ah[o1], ah2 = Ah[o0 + 4], ah3 = Ah[o1 + 4];
                uint32_t al0 = Al[o0], al1 = Al[o1], al2 = Al[o0 + 4], al3 = Al[o1 + 4];
#pragma unroll
                for (int j = 0; j < 4; j++) {
                    MMA(acc[i][j], ah0, ah1, ah2, ah3, bh[j][0], bh[j][1]);
                    MMA(acc[i][j], ah0, ah1, ah2, ah3, bl[j][0], bl[j][1]);
                    MMA(acc[i][j], al0, al1, al2, al3, bh[j][0], bh[j][1]);
                }
            }
        }
        if (kt + 1 < KT) STORE_REGS((kt + 1) & 1);     // other buffer: no hazard with compute
    }

#pragma unroll
    for (int i = 0; i < 4; i++) {
#pragma unroll
        for (int j = 0; j < 4; j++) {
            int col = bn + wn + 8 * j + 2 * c;
            int row0 = bm + wm + 16 * i + r;
            float b0 = bias[col], b1 = bias[col + 1];
            float v0 = acc[i][j][0] + b0, v1 = acc[i][j][1] + b1;
            float v2 = acc[i][j][2] + b0, v3 = acc[i][j][3] + b1;
            if (relu) {
                v0 = fmaxf(v0, 0.0f); v1 = fmaxf(v1, 0.0f);
                v2 = fmaxf(v2, 0.0f); v3 = fmaxf(v3, 0.0f);
            }
            *(float2*)(C + (size_t)row0 * N + col) = make_float2(v0, v1);
            *(float2*)(C + (size_t)(row0 + 8) * N + col) = make_float2(v2, v3);
        }
    }
}

// ============ fused flash attention (split-bf16 HMMA, online softmax, 1e-19 mask quirk) ============
#define FA_SMEM_WORDS (4608 + 4608 + 4352 + 4352)
#define FA_SMEM_BYTES (FA_SMEM_WORDS * 4)
__global__ __launch_bounds__(256) void flash_attn(const float* __restrict__ Qg,
                                                  const float* __restrict__ Kg,
                                                  const float* __restrict__ Vg,
                                                  float* __restrict__ Og, int causal) {
    extern __shared__ uint32_t sm[];
    uint32_t* Kh = sm;
    uint32_t* Kl = sm + 4608;
    uint32_t* Vh = sm + 9216;
    uint32_t* Vl = sm + 13568;
    int tid = threadIdx.x, wid = tid >> 5, lane = tid & 31;
    int r = lane >> 2, c = lane & 3;
    int b = blockIdx.y >> 4, h = blockIdx.y & 15;
    const float* Qb = Qg + (size_t)b * SEQ * DEMB + h * DH;
    const float* Kb = Kg + (size_t)b * SEQ * DEMB + h * DH;
    const float* Vb = Vg + (size_t)b * SEQ * DEMB + h * DH;
    int q0 = blockIdx.x * 128;
    int grow = q0 + wid * 16 + r;

    uint32_t qh[4][4], ql[4][4];
#pragma unroll
    for (int s = 0; s < 4; s++) {
        const float* q0p = Qb + (size_t)grow * DEMB + s * 16;
        const float* q1p = q0p + 8 * DEMB;
        float2 v0 = *(const float2*)(q0p + 2 * c);
        float2 v1 = *(const float2*)(q1p + 2 * c);
        float2 v2 = *(const float2*)(q0p + 2 * c + 8);
        float2 v3 = *(const float2*)(q1p + 2 * c + 8);
        split2(v0.x, v0.y, qh[s][0], ql[s][0]);
        split2(v1.x, v1.y, qh[s][1], ql[s][1]);
        split2(v2.x, v2.y, qh[s][2], ql[s][2]);
        split2(v3.x, v3.y, qh[s][3], ql[s][3]);
    }

    float oacc[8][4] = {};
    float m0 = -1e30f, m1 = -1e30f, l0 = 0.0f, l1 = 0.0f;

    for (int kt = 0; kt < SEQ / 128; kt++) {
        int k0 = kt * 128;
        __syncthreads();
#pragma unroll
        for (int p = 0; p < 16; p++) {
            int idx = tid + p * 256;
            int row = idx >> 5, kp = idx & 31;
            float2 kv = *(const float2*)(Kb + (size_t)(k0 + row) * DEMB + kp * 2);
            uint32_t hh, ll; split2(kv.x, kv.y, hh, ll);
            Kh[row * 36 + kp] = hh; Kl[row * 36 + kp] = ll;
        }
#pragma unroll
        for (int p = 0; p < 16; p++) {
            int idx = tid + p * 256;
            int d = idx & 63, kp = idx >> 6;
            float x0 = Vb[(size_t)(k0 + kp * 2) * DEMB + d];
            float x1 = Vb[(size_t)(k0 + kp * 2 + 1) * DEMB + d];
            uint32_t hh, ll; split2(x0, x1, hh, ll);
            Vh[d * 68 + kp] = hh; Vl[d * 68 + kp] = ll;
        }
        __syncthreads();

        float sacc[16][4];
#pragma unroll
        for (int j = 0; j < 16; j++) { sacc[j][0] = sacc[j][1] = sacc[j][2] = sacc[j][3] = 0.0f; }
#pragma unroll
        for (int j = 0; j < 16; j++) {
#pragma unroll
            for (int s = 0; s < 4; s++) {
                int o = (8 * j + r) * 36 + 8 * s + c;
                uint32_t kh0 = Kh[o], kh1 = Kh[o + 4];
                uint32_t kl0 = Kl[o], kl1 = Kl[o + 4];
                MMA(sacc[j], qh[s][0], qh[s][1], qh[s][2], qh[s][3], kh0, kh1);
                MMA(sacc[j], qh[s][0], qh[s][1], qh[s][2], qh[s][3], kl0, kl1);
                MMA(sacc[j], ql[s][0], ql[s][1], ql[s][2], ql[s][3], kh0, kh1);
            }
        }
        float tm0 = -1e30f, tm1 = -1e30f;
#pragma unroll
        for (int j = 0; j < 16; j++) {
            int col = k0 + 8 * j + 2 * c;
            float v0 = sacc[j][0] * 0.125f, v1 = sacc[j][1] * 0.125f;
            float v2 = sacc[j][2] * 0.125f, v3 = sacc[j][3] * 0.125f;
            if (causal) {
                if (col     > grow)     v0 = 1e-19f;
                if (col + 1 > grow)     v1 = 1e-19f;
                if (col     > grow + 8) v2 = 1e-19f;
                if (col + 1 > grow + 8) v3 = 1e-19f;
            }
            sacc[j][0] = v0; sacc[j][1] = v1; sacc[j][2] = v2; sacc[j][3] = v3;
            tm0 = fmaxf(tm0, fmaxf(v0, v1));
            tm1 = fmaxf(tm1, fmaxf(v2, v3));
        }
        tm0 = fmaxf(tm0, __shfl_xor_sync(0xffffffffu, tm0, 1));
        tm0 = fmaxf(tm0, __shfl_xor_sync(0xffffffffu, tm0, 2));
        tm1 = fmaxf(tm1, __shfl_xor_sync(0xffffffffu, tm1, 1));
        tm1 = fmaxf(tm1, __shfl_xor_sync(0xffffffffu, tm1, 2));
        float mn0 = fmaxf(m0, tm0), mn1 = fmaxf(m1, tm1);
        float sc0 = __expf(m0 - mn0), sc1 = __expf(m1 - mn1);
        m0 = mn0; m1 = mn1;
        float rs0 = 0.0f, rs1 = 0.0f;
#pragma unroll
        for (int j = 0; j < 16; j++) {
            float p0 = __expf(sacc[j][0] - m0), p1 = __expf(sacc[j][1] - m0);
            float p2 = __expf(sacc[j][2] - m1), p3 = __expf(sacc[j][3] - m1);
            sacc[j][0] = p0; sacc[j][1] = p1; sacc[j][2] = p2; sacc[j][3] = p3;
            rs0 += p0 + p1; rs1 += p2 + p3;
        }
        rs0 += __shfl_xor_sync(0xffffffffu, rs0, 1);
        rs0 += __shfl_xor_sync(0xffffffffu, rs0, 2);
        rs1 += __shfl_xor_sync(0xffffffffu, rs1, 1);
        rs1 += __shfl_xor_sync(0xffffffffu, rs1, 2);
        l0 = l0 * sc0 + rs0; l1 = l1 * sc1 + rs1;
#pragma unroll
        for (int j2 = 0; j2 < 8; j2++) {
            oacc[j2][0] *= sc0; oacc[j2][1] *= sc0;
            oacc[j2][2] *= sc1; oacc[j2][3] *= sc1;
        }
#pragma unroll
        for (int s2 = 0; s2 < 8; s2++) {
            uint32_t a0h, a0l, a1h, a1l, a2h, a2l, a3h, a3l;
            split2(sacc[2 * s2][0],     sacc[2 * s2][1],     a0h, a0l);
            split2(sacc[2 * s2][2],     sacc[2 * s2][3],     a1h, a1l);
            split2(sacc[2 * s2 + 1][0], sacc[2 * s2 + 1][1], a2h, a2l);
            split2(sacc[2 * s2 + 1][2], sacc[2 * s2 + 1][3], a3h, a3l);
#pragma unroll
            for (int j2 = 0; j2 < 8; j2++) {
                int o = (8 * j2 + r) * 68 + 8 * s2 + c;
                uint32_t vh0 = Vh[o], vh1 = Vh[o + 4];
                uint32_t vl0 = Vl[o], vl1 = Vl[o + 4];
                MMA(oacc[j2], a0h, a1h, a2h, a3h, vh0, vh1);
                MMA(oacc[j2], a0h, a1h, a2h, a3h, vl0, vl1);
                MMA(oacc[j2], a0l, a1l, a2l, a3l, vh0, vh1);
            }
        }
    }
    float i0 = 1.0f / l0, i1 = 1.0f / l1;
#pragma unroll
    for (int j2 = 0; j2 < 8; j2++) {
        float* op = Og + (size_t)(b * SEQ + grow) * DEMB + h * DH + 8 * j2 + 2 * c;
        *(float2*)op = make_float2(oacc[j2][0] * i0, oacc[j2][1] * i0);
        *(float2*)(op + 8 * DEMB) = make_float2(oacc[j2][2] * i1, oacc[j2][3] * i1);
    }
}

// ---------------- embedding + positional encoding ----------------
__global__ __launch_bounds__(256) void embed_kernel(const int* __restrict__ ids,
                                                    const float* __restrict__ emb,
                                                    float* __restrict__ X) {
    int t = blockIdx.x;
    int pos = t & (SEQ - 1);
    int id = ids[t];
    int d0 = threadIdx.x * 4;
    float4 e4 = *(const float4*)(emb + (size_t)id * DEMB + d0);
    float ev[4] = {e4.x, e4.y, e4.z, e4.w};
    float ov[4];
#pragma unroll
    for (int j = 0; j < 4; j++) {
        int d = d0 + j;
        float ang = (float)pos * powf(10000.0f, -2.0f * (float)d / (float)DEMB);
        float pe = ((d & 1) == 0) ? sinf(ang) : cosf(ang);
        ov[j] = ev[j] * 32.0f + pe;
    }
    *(float4*)(X + (size_t)t * DEMB + d0) = make_float4(ov[0], ov[1], ov[2], ov[3]);
}

// ---------------- fused q/k/v per-head projection (grid.z selects) ----------------
__global__ __launch_bounds__(256) void proj_head3(
        const float* __restrict__ X0, const float* __restrict__ X1, const float* __restrict__ X2,
        const float* __restrict__ W0, const float* __restrict__ W1, const float* __restrict__ W2,
        float* __restrict__ O0, float* __restrict__ O1, float* __restrict__ O2) {
    const float* X; const float* W; float* O;
    if (blockIdx.z == 0)      { X = X0; W = W0; O = O0; }
    else if (blockIdx.z == 1) { X = X1; W = W1; O = O1; }
    else                      { X = X2; W = W2; O = O2; }
    __shared__ float Xs[64][64];
    __shared__ float Ws[64][64];
    int tid = threadIdx.x;
    int h = blockIdx.y;
    int t0 = blockIdx.x * 64;
#pragma unroll
    for (int r = 0; r < 4; r++) {
        int idx = tid + r * 256;
        int a = idx >> 4;
        int c4 = (idx & 15) << 2;
        float4 xv = *(const float4*)(X + (size_t)(t0 + a) * DEMB + h * DH + c4);
        Xs[c4 + 0][a] = xv.x; Xs[c4 + 1][a] = xv.y; Xs[c4 + 2][a] = xv.z; Xs[c4 + 3][a] = xv.w;
        float4 wv = *(const float4*)(W + a * DH + c4);
        *(float4*)&Ws[a][c4] = wv;
    }
    __syncthreads();
    int tx = tid & 15, ty = tid >> 4;
    float acc[4][4] = {};
#pragma unroll
    for (int d = 0; d < 64; d++) {
        float4 a4 = *(float4*)&Xs[d][ty * 4];
        float4 w4 = *(float4*)&Ws[d][tx * 4];
        float av[4] = {a4.x, a4.y, a4.z, a4.w};
        float wv[4] = {w4.x, w4.y, w4.z, w4.w};
#pragma unroll
        for (int i = 0; i < 4; i++)
#pragma unroll
            for (int j = 0; j < 4; j++) acc[i][j] = fmaf(av[i], wv[j], acc[i][j]);
    }
#pragma unroll
    for (int i = 0; i < 4; i++) {
        float4 o = make_float4(acc[i][0], acc[i][1], acc[i][2], acc[i][3]);
        *(float4*)(O + (size_t)(t0 + ty * 4 + i) * DEMB + h * DH + tx * 4) = o;
    }
}

// ---------------- residual add + layernorm: one warp per row, shuffle-only ----------------
__global__ __launch_bounds__(256) void add_ln(const float* __restrict__ A, const float* __restrict__ B,
                                              const float* __restrict__ g, const float* __restrict__ be,
                                              float* __restrict__ O) {
    int lane = threadIdx.x & 31, wid = threadIdx.x >> 5;
    int row = blockIdx.x * 8 + wid;
    size_t base = (size_t)row * DEMB;
    float4 v[8];
    float s1 = 0.0f, s2 = 0.0f;
#pragma unroll
    for (int p = 0; p < 8; p++) {
        float4 a = ((const float4*)(A + base))[lane + p * 32];
        float4 b = ((const float4*)(B + base))[lane + p * 32];
        float4 t = make_float4(a.x + b.x, a.y + b.y, a.z + b.z, a.w + b.w);
        v[p] = t;
        s1 += t.x + t.y + t.z + t.w;
        s2 += t.x * t.x + t.y * t.y + t.z * t.z + t.w * t.w;
    }
#pragma unroll
    for (int o = 16; o; o >>= 1) {
        s1 += __shfl_xor_sync(0xffffffffu, s1, o);
        s2 += __shfl_xor_sync(0xffffffffu, s2, o);
    }
    float mu = s1 * (1.0f / DEMB);
    float var = s2 * (1.0f / DEMB) - mu * mu;
    float w = rsqrtf(var + 1e-5f);
#pragma unroll
    for (int p = 0; p < 8; p++) {
        float4 gg = ((const float4*)g)[lane + p * 32];
        float4 bb = ((const float4*)be)[lane + p * 32];
        float4 t = v[p];
        float4 o;
        o.x = (t.x - mu) * w * gg.x + bb.x;
        o.y = (t.y - mu) * w * gg.y + bb.y;
        o.z = (t.z - mu) * w * gg.z + bb.z;
        o.w = (t.w - mu) * w * gg.w + bb.w;
        ((float4*)(O + base))[lane + p * 32] = o;
    }
}

// ---------------- host orchestration ----------------
extern "C" void kernel_launch(void* const* d_in, const int* in_sizes, int n_in,
                              void* d_out, int out_size) {
    const int*   ids   = (const int*)  d_in[0];
    const float* enc_k = (const float*)d_in[1];
    const float* enc_v = (const float*)d_in[2];
    const float* emb   = (const float*)d_in[3];
    const float* Wq_m  = (const float*)d_in[4];
    const float* Wk_m  = (const float*)d_in[5];
    const float* Wv_m  = (const float*)d_in[6];
    const float* Wq_c  = (const float*)d_in[7];
    const float* Wk_c  = (const float*)d_in[8];
    const float* Wv_c  = (const float*)d_in[9];
    const float* ln1_g = (const float*)d_in[10];
    const float* ln1_b = (const float*)d_in[11];
    const float* ln2_g = (const float*)d_in[12];
    const float* ln2_b = (const float*)d_in[13];
    const float* ln3_g = (const float*)d_in[14];
    const float* ln3_b = (const float*)d_in[15];
    const float* W1    = (const float*)d_in[16];
    const float* b1    = (const float*)d_in[17];
    const float* W2    = (const float*)d_in[18];
    const float* b2    = (const float*)d_in[19];
    const float* Wout  = (const float*)d_in[20];
    const float* bout  = (const float*)d_in[21];
    float* out = (float*)d_out;

    float *x, *h1, *h2, *t, *q, *k, *v, *ff;
    cudaGetSymbolAddress((void**)&x,  g_x);
    cudaGetSymbolAddress((void**)&h1, g_h1);
    cudaGetSymbolAddress((void**)&h2, g_h2);
    cudaGetSymbolAddress((void**)&t,  g_t);
    cudaGetSymbolAddress((void**)&q,  g_q);
    cudaGetSymbolAddress((void**)&k,  g_k);
    cudaGetSymbolAddress((void**)&v,  g_v);
    cudaGetSymbolAddress((void**)&ff, g_ff);

    cudaFuncSetAttribute(flash_attn, cudaFuncAttributeMaxDynamicSharedMemorySize, FA_SMEM_BYTES);
    cudaFuncSetAttribute(gemm_hmma, cudaFuncAttributeMaxDynamicSharedMemorySize, GEMM_SMEM);

    dim3 blk(256);
    dim3 projGrid(NTOK / 64, NHEAD, 3);
    dim3 faGrid(SEQ / 128, NB * NHEAD);

    embed_kernel<<<NTOK, blk>>>(ids, emb, x);

    for (int l = 0; l < NLAYER; l++) {
        size_t wOff  = (size_t)l * DH * DH;
        size_t lnOff = (size_t)l * DEMB;
        // --- masked self-attention ---
        proj_head3<<<projGrid, blk>>>(x, x, x, Wq_m + wOff, Wk_m + wOff, Wv_m + wOff, q, k, v);
        flash_attn<<<faGrid, blk, FA_SMEM_BYTES>>>(q, k, v, t, 1);
        add_ln<<<NTOK / 8, blk>>>(t, x, ln1_g + lnOff, ln1_b + lnOff, h1);
        // --- cross-attention ---
        proj_head3<<<projGrid, blk>>>(h1, enc_k, enc_v, Wq_c + wOff, Wk_c + wOff, Wv_c + wOff, q, k, v);
        flash_attn<<<faGrid, blk, FA_SMEM_BYTES>>>(q, k, v, t, 0);
        add_ln<<<NTOK / 8, blk>>>(t, h1, ln2_g + lnOff, ln2_b + lnOff, h2);
        // --- FFN (pipelined split-bf16 HMMA, 2 CTAs/SM) ---
        gemm_hmma<<<dim3(NTOK / 128, DFF / 128), blk, GEMM_SMEM>>>(
            h2, W1 + (size_t)l * DEMB * DFF, b1 + (size_t)l * DFF, ff, DFF, DEMB, 1);
        gemm_hmma<<<dim3(NTOK / 128, DEMB / 128), blk, GEMM_SMEM>>>(
            ff, W2 + (size_t)l * DFF * DEMB, b2 + lnOff, t, DEMB, DFF, 0);
        add_ln<<<NTOK / 8, blk>>>(t, h2, ln3_g + lnOff, ln3_b + lnOff, x);
    }

    gemm_hmma<<<dim3(NTOK / 128, NVOCAB / 128), blk, GEMM_SMEM>>>(
        x, Wout, bout, out, NVOCAB, DEMB, 0);
}

// round 7
// speedup vs baseline: 1.1304x; 1.1304x over previous
#include <cuda_runtime.h>
#include <cuda_bf16.h>
#include <math.h>
#include <stdint.h>

#define NB 2
#define SEQ 1024
#define NTOK (NB * SEQ)          // 2048
#define DEMB 1024
#define NHEAD 16
#define DH 64
#define DFF 4096
#define NVOCAB 32000
#define NLAYER 6

// -------- scratch (device globals; no allocation allowed) --------
__device__ float g_x [NTOK * DEMB];
__device__ float g_h1[NTOK * DEMB];
__device__ float g_h2[NTOK * DEMB];
__device__ float g_t [NTOK * DEMB];
__device__ float g_q [NTOK * DEMB];
__device__ float g_k [NTOK * DEMB];
__device__ float g_v [NTOK * DEMB];
__device__ float g_ff[NTOK * DFF];
// split-bf16 staging (uint16 = raw bf16 bits)
__device__ uint16_t g_ah [NTOK * DFF];        // A hi (max 2048x4096)
__device__ uint16_t g_al [NTOK * DFF];        // A lo
__device__ uint16_t g_bth[(size_t)NVOCAB * DEMB];  // B^T hi (max 32000x1024)
__device__ uint16_t g_btl[(size_t)NVOCAB * DEMB];  // B^T lo

// ---------------- split-bf16 helper: x = hi(bf16) + lo(bf16), hi exact-truncate ----------------
__device__ __forceinline__ void split2(float x0, float x1, uint32_t& hi, uint32_t& lo) {
    uint32_t u0 = __float_as_uint(x0), u1 = __float_as_uint(x1);
    hi = __byte_perm(u0, u1, 0x7632);                    // {bf16(x1), bf16(x0)} truncated
    float l0 = x0 - __uint_as_float(u0 & 0xffff0000u);   // exact
    float l1 = x1 - __uint_as_float(u1 & 0xffff0000u);
    asm("cvt.rn.bf16x2.f32 %0, %1, %2;" : "=r"(lo) : "f"(l1), "f"(l0));
}

#define MMA(acc, a0, a1, a2, a3, b0, b1)                                        \
    asm("mma.sync.aligned.m16n8k16.row.col.f32.bf16.bf16.f32 "                  \
        "{%0,%1,%2,%3}, {%4,%5,%6,%7}, {%8,%9}, {%0,%1,%2,%3};"                 \
        : "+f"((acc)[0]), "+f"((acc)[1]), "+f"((acc)[2]), "+f"((acc)[3])        \
        : "r"(a0), "r"(a1), "r"(a2), "r"(a3), "r"(b0), "r"(b1))

#define CP_ASYNC16(dst, src) \
    asm volatile("cp.async.cg.shared.global [%0], [%1], 16;" :: "r"(dst), "l"(src))
#define CP_COMMIT() asm volatile("cp.async.commit_group;")
#define CP_WAIT(n)  asm volatile("cp.async.wait_group %0;" :: "n"(n))

__device__ __forceinline__ uint32_t smem_u32(const void* p) {
    uint32_t a;
    asm("{ .reg .u64 t; cvta.to.shared.u64 t, %1; cvt.u32.u64 %0, t; }" : "=r"(a) : "l"(p));
    return a;
}

// ---------------- elementwise fp32 -> split-bf16 (hi/lo) ----------------
__global__ __launch_bounds__(256) void cvt_split(const float* __restrict__ in,
                                                 uint16_t* __restrict__ hi,
                                                 uint16_t* __restrict__ lo) {
    int i4 = (blockIdx.x * 256 + threadIdx.x) * 4;
    float4 v = *(const float4*)(in + i4);
    uint32_t h0, l0, h1, l1;
    split2(v.x, v.y, h0, l0);
    split2(v.z, v.w, h1, l1);
    *(uint32_t*)(hi + i4) = h0; *(uint32_t*)(hi + i4 + 2) = h1;
    *(uint32_t*)(lo + i4) = l0; *(uint32_t*)(lo + i4 + 2) = l1;
}

// ---------------- transpose + split: in[K][N] -> hiT/loT [N][K] ----------------
__global__ __launch_bounds__(256) void cvt_trans(const float* __restrict__ in,
                                                 uint16_t* __restrict__ hiT,
                                                 uint16_t* __restrict__ loT,
                                                 int K, int N) {
    __shared__ float t[32][33];
    int n0 = blockIdx.x * 32, k0 = blockIdx.y * 32;
    int tx = threadIdx.x & 31, ty = threadIdx.x >> 5;   // 32x8
#pragma unroll
    for (int i = 0; i < 32; i += 8)
        t[ty + i][tx] = in[(size_t)(k0 + ty + i) * N + n0 + tx];
    __syncthreads();
#pragma unroll
    for (int i = 0; i < 32; i += 8) {
        float x = t[tx][ty + i];                         // k = k0+tx, n = n0+ty+i
        uint32_t u = __float_as_uint(x);
        float l = x - __uint_as_float(u & 0xffff0000u);
        uint16_t lb;
        { __nv_bfloat16 b = __float2bfloat16(l); lb = *(uint16_t*)&b; }
        size_t o = (size_t)(n0 + ty + i) * K + k0 + tx;
        hiT[o] = (uint16_t)(u >> 16);
        loT[o] = lb;
    }
}

// ============ cp.async pipelined split-bf16 HMMA GEMM: C = A@B^T(pre-split) + bias ============
// A: [M][K] hi/lo bf16, Bt: [N][K] hi/lo bf16. grid=(M/128,N/128), block=256, 2 CTAs/SM.
#define STRIDE 20                         // words per smem row (32 k + pad)
#define TILE_B (128 * STRIDE * 4)         // 10240 bytes per tile
#define BUF_B  (4 * TILE_B)               // Ah,Al,Bh,Bl = 40960 bytes
#define GEMM_SMEM (2 * BUF_B)             // 81920

__global__ __launch_bounds__(256, 2) void gemm_cp(const uint16_t* __restrict__ Ahg,
                                                  const uint16_t* __restrict__ Alg,
                                                  const uint16_t* __restrict__ Bth,
                                                  const uint16_t* __restrict__ Btl,
                                                  const float* __restrict__ bias,
                                                  float* __restrict__ C,
                                                  int N, int K, int relu) {
    extern __shared__ uint32_t sh[];
    uint32_t sb = smem_u32(sh);
    int tid = threadIdx.x, wid = tid >> 5, lane = tid & 31;
    int bm = blockIdx.x * 128, bn = blockIdx.y * 128;
    int wm = (wid >> 2) * 64, wn = (wid & 3) * 32;
    int r = lane >> 2, c = lane & 3;

#define ISSUE(kt, buf)                                                          \
    {                                                                           \
        int k0i = (kt) << 5;                                                    \
        _Pragma("unroll")                                                       \
        for (int p = 0; p < 2; p++) {                                           \
            int idx = tid + p * 256;                                            \
            int row = idx >> 2, q = idx & 3;                                    \
            size_t ao = (size_t)(bm + row) * K + k0i + q * 8;                   \
            size_t bo = (size_t)(bn + row) * K + k0i + q * 8;                   \
            uint32_t d = sb + (buf) * BUF_B + row * (STRIDE * 4) + q * 16;      \
            CP_ASYNC16(d,              Ahg + ao);                               \
            CP_ASYNC16(d + TILE_B,     Alg + ao);                               \
            CP_ASYNC16(d + 2 * TILE_B, Bth + bo);                               \
            CP_ASYNC16(d + 3 * TILE_B, Btl + bo);                               \
        }                                                                       \
        CP_COMMIT();                                                            \
    }

    float acc[4][4][4] = {};

    int KT = K >> 5;
    ISSUE(0, 0);
    ISSUE(1, 1);

    for (int kt = 0; kt < KT; kt++) {
        if (kt + 1 < KT) { CP_WAIT(1); } else { CP_WAIT(0); }
        __syncthreads();
        uint32_t* Ah = sh + (kt & 1) * (BUF_B / 4);
        uint32_t* Al = Ah + 2560;
        uint32_t* Bh = Al + 2560;
        uint32_t* Bl = Bh + 2560;
#pragma unroll
        for (int s = 0; s < 2; s++) {
            uint32_t bh[4][2], bl[4][2];
#pragma unroll
            for (int j = 0; j < 4; j++) {
                int o = (wn + 8 * j + r) * STRIDE + s * 8 + c;
                bh[j][0] = Bh[o]; bh[j][1] = Bh[o + 4];
                bl[j][0] = Bl[o]; bl[j][1] = Bl[o + 4];
            }
#pragma unroll
            for (int i = 0; i < 4; i++) {
                int o0 = (wm + 16 * i + r) * STRIDE + s * 8 + c;
                int o1 = o0 + 8 * STRIDE;
                uint32_t ah0 = Ah[o0], ah1 = Ah[o1], ah2 = Ah[o0 + 4], ah3 = Ah[o1 + 4];
                uint32_t al0 = Al[o0], al1 = Al[o1], al2 = Al[o0 + 4], al3 = Al[o1 + 4];
#pragma unroll
                for (int j = 0; j < 4; j++) {
                    MMA(acc[i][j], ah0, ah1, ah2, ah3, bh[j][0], bh[j][1]);
                    MMA(acc[i][j], ah0, ah1, ah2, ah3, bl[j][0], bl[j][1]);
                    MMA(acc[i][j], al0, al1, al2, al3, bh[j][0], bh[j][1]);
                }
            }
        }
        if (kt + 2 < KT) {
            __syncthreads();               // all compute(kt) done before overwriting its buffer
            ISSUE(kt + 2, kt & 1);
        }
    }

#pragma unroll
    for (int i = 0; i < 4; i++) {
#pragma unroll
        for (int j = 0; j < 4; j++) {
            int col = bn + wn + 8 * j + 2 * c;
            int row0 = bm + wm + 16 * i + r;
            float b0 = bias[col], b1 = bias[col + 1];
            float v0 = acc[i][j][0] + b0, v1 = acc[i][j][1] + b1;
            float v2 = acc[i][j][2] + b0, v3 = acc[i][j][3] + b1;
            if (relu) {
                v0 = fmaxf(v0, 0.0f); v1 = fmaxf(v1, 0.0f);
                v2 = fmaxf(v2, 0.0f); v3 = fmaxf(v3, 0.0f);
            }
            *(float2*)(C + (size_t)row0 * N + col) = make_float2(v0, v1);
            *(float2*)(C + (size_t)(row0 + 8) * N + col) = make_float2(v2, v3);
        }
    }
}

// ============ fused flash attention (split-bf16 HMMA, online softmax, 1e-19 mask quirk) ============
#define FA_SMEM_WORDS (4608 + 4608 + 4352 + 4352)
#define FA_SMEM_BYTES (FA_SMEM_WORDS * 4)
__global__ __launch_bounds__(256) void flash_attn(const float* __restrict__ Qg,
                                                  const float* __restrict__ Kg,
                                                  const float* __restrict__ Vg,
                                                  float* __restrict__ Og, int causal) {
    extern __shared__ uint32_t sm[];
    uint32_t* Kh = sm;
    uint32_t* Kl = sm + 4608;
    uint32_t* Vh = sm + 9216;
    uint32_t* Vl = sm + 13568;
    int tid = threadIdx.x, wid = tid >> 5, lane = tid & 31;
    int r = lane >> 2, c = lane & 3;
    int b = blockIdx.y >> 4, h = blockIdx.y & 15;
    const float* Qb = Qg + (size_t)b * SEQ * DEMB + h * DH;
    const float* Kb = Kg + (size_t)b * SEQ * DEMB + h * DH;
    const float* Vb = Vg + (size_t)b * SEQ * DEMB + h * DH;
    int q0 = blockIdx.x * 128;
    int grow = q0 + wid * 16 + r;

    uint32_t qh[4][4], ql[4][4];
#pragma unroll
    for (int s = 0; s < 4; s++) {
        const float* q0p = Qb + (size_t)grow * DEMB + s * 16;
        const float* q1p = q0p + 8 * DEMB;
        float2 v0 = *(const float2*)(q0p + 2 * c);
        float2 v1 = *(const float2*)(q1p + 2 * c);
        float2 v2 = *(const float2*)(q0p + 2 * c + 8);
        float2 v3 = *(const float2*)(q1p + 2 * c + 8);
        split2(v0.x, v0.y, qh[s][0], ql[s][0]);
        split2(v1.x, v1.y, qh[s][1], ql[s][1]);
        split2(v2.x, v2.y, qh[s][2], ql[s][2]);
        split2(v3.x, v3.y, qh[s][3], ql[s][3]);
    }

    float oacc[8][4] = {};
    float m0 = -1e30f, m1 = -1e30f, l0 = 0.0f, l1 = 0.0f;

    for (int kt = 0; kt < SEQ / 128; kt++) {
        int k0 = kt * 128;
        __syncthreads();
#pragma unroll
        for (int p = 0; p < 16; p++) {
            int idx = tid + p * 256;
            int row = idx >> 5, kp = idx & 31;
            float2 kv = *(const float2*)(Kb + (size_t)(k0 + row) * DEMB + kp * 2);
            uint32_t hh, ll; split2(kv.x, kv.y, hh, ll);
            Kh[row * 36 + kp] = hh; Kl[row * 36 + kp] = ll;
        }
#pragma unroll
        for (int p = 0; p < 16; p++) {
            int idx = tid + p * 256;
            int d = idx & 63, kp = idx >> 6;
            float x0 = Vb[(size_t)(k0 + kp * 2) * DEMB + d];
            float x1 = Vb[(size_t)(k0 + kp * 2 + 1) * DEMB + d];
            uint32_t hh, ll; split2(x0, x1, hh, ll);
            Vh[d * 68 + kp] = hh; Vl[d * 68 + kp] = ll;
        }
        __syncthreads();

        float sacc[16][4];
#pragma unroll
        for (int j = 0; j < 16; j++) { sacc[j][0] = sacc[j][1] = sacc[j][2] = sacc[j][3] = 0.0f; }
#pragma unroll
        for (int j = 0; j < 16; j++) {
#pragma unroll
            for (int s = 0; s < 4; s++) {
                int o = (8 * j + r) * 36 + 8 * s + c;
                uint32_t kh0 = Kh[o], kh1 = Kh[o + 4];
                uint32_t kl0 = Kl[o], kl1 = Kl[o + 4];
                MMA(sacc[j], qh[s][0], qh[s][1], qh[s][2], qh[s][3], kh0, kh1);
                MMA(sacc[j], qh[s][0], qh[s][1], qh[s][2], qh[s][3], kl0, kl1);
                MMA(sacc[j], ql[s][0], ql[s][1], ql[s][2], ql[s][3], kh0, kh1);
            }
        }
        float tm0 = -1e30f, tm1 = -1e30f;
#pragma unroll
        for (int j = 0; j < 16; j++) {
            int col = k0 + 8 * j + 2 * c;
            float v0 = sacc[j][0] * 0.125f, v1 = sacc[j][1] * 0.125f;
            float v2 = sacc[j][2] * 0.125f, v3 = sacc[j][3] * 0.125f;
            if (causal) {
                if (col     > grow)     v0 = 1e-19f;
                if (col + 1 > grow)     v1 = 1e-19f;
                if (col     > grow + 8) v2 = 1e-19f;
                if (col + 1 > grow + 8) v3 = 1e-19f;
            }
            sacc[j][0] = v0; sacc[j][1] = v1; sacc[j][2] = v2; sacc[j][3] = v3;
            tm0 = fmaxf(tm0, fmaxf(v0, v1));
            tm1 = fmaxf(tm1, fmaxf(v2, v3));
        }
        tm0 = fmaxf(tm0, __shfl_xor_sync(0xffffffffu, tm0, 1));
        tm0 = fmaxf(tm0, __shfl_xor_sync(0xffffffffu, tm0, 2));
        tm1 = fmaxf(tm1, __shfl_xor_sync(0xffffffffu, tm1, 1));
        tm1 = fmaxf(tm1, __shfl_xor_sync(0xffffffffu, tm1, 2));
        float mn0 = fmaxf(m0, tm0), mn1 = fmaxf(m1, tm1);
        float sc0 = __expf(m0 - mn0), sc1 = __expf(m1 - mn1);
        m0 = mn0; m1 = mn1;
        float rs0 = 0.0f, rs1 = 0.0f;
#pragma unroll
        for (int j = 0; j < 16; j++) {
            float p0 = __expf(sacc[j][0] - m0), p1 = __expf(sacc[j][1] - m0);
            float p2 = __expf(sacc[j][2] - m1), p3 = __expf(sacc[j][3] - m1);
            sacc[j][0] = p0; sacc[j][1] = p1; sacc[j][2] = p2; sacc[j][3] = p3;
            rs0 += p0 + p1; rs1 += p2 + p3;
        }
        rs0 += __shfl_xor_sync(0xffffffffu, rs0, 1);
        rs0 += __shfl_xor_sync(0xffffffffu, rs0, 2);
        rs1 += __shfl_xor_sync(0xffffffffu, rs1, 1);
        rs1 += __shfl_xor_sync(0xffffffffu, rs1, 2);
        l0 = l0 * sc0 + rs0; l1 = l1 * sc1 + rs1;
#pragma unroll
        for (int j2 = 0; j2 < 8; j2++) {
            oacc[j2][0] *= sc0; oacc[j2][1] *= sc0;
            oacc[j2][2] *= sc1; oacc[j2][3] *= sc1;
        }
#pragma unroll
        for (int s2 = 0; s2 < 8; s2++) {
            uint32_t a0h, a0l, a1h, a1l, a2h, a2l, a3h, a3l;
            split2(sacc[2 * s2][0],     sacc[2 * s2][1],     a0h, a0l);
            split2(sacc[2 * s2][2],     sacc[2 * s2][3],     a1h, a1l);
            split2(sacc[2 * s2 + 1][0], sacc[2 * s2 + 1][1], a2h, a2l);
            split2(sacc[2 * s2 + 1][2], sacc[2 * s2 + 1][3], a3h, a3l);
#pragma unroll
            for (int j2 = 0; j2 < 8; j2++) {
                int o = (8 * j2 + r) * 68 + 8 * s2 + c;
                uint32_t vh0 = Vh[o], vh1 = Vh[o + 4];
                uint32_t vl0 = Vl[o], vl1 = Vl[o + 4];
                MMA(oacc[j2], a0h, a1h, a2h, a3h, vh0, vh1);
                MMA(oacc[j2], a0h, a1h, a2h, a3h, vl0, vl1);
                MMA(oacc[j2], a0l, a1l, a2l, a3l, vh0, vh1);
            }
        }
    }
    float i0 = 1.0f / l0, i1 = 1.0f / l1;
#pragma unroll
    for (int j2 = 0; j2 < 8; j2++) {
        float* op = Og + (size_t)(b * SEQ + grow) * DEMB + h * DH + 8 * j2 + 2 * c;
        *(float2*)op = make_float2(oacc[j2][0] * i0, oacc[j2][1] * i0);
        *(float2*)(op + 8 * DEMB) = make_float2(oacc[j2][2] * i1, oacc[j2][3] * i1);
    }
}

// ---------------- embedding + positional encoding ----------------
__global__ __launch_bounds__(256) void embed_kernel(const int* __restrict__ ids,
                                                    const float* __restrict__ emb,
                                                    float* __restrict__ X) {
    int t = blockIdx.x;
    int pos = t & (SEQ - 1);
    int id = ids[t];
    int d0 = threadIdx.x * 4;
    float4 e4 = *(const float4*)(emb + (size_t)id * DEMB + d0);
    float ev[4] = {e4.x, e4.y, e4.z, e4.w};
    float ov[4];
#pragma unroll
    for (int j = 0; j < 4; j++) {
        int d = d0 + j;
        float ang = (float)pos * powf(10000.0f, -2.0f * (float)d / (float)DEMB);
        float pe = ((d & 1) == 0) ? sinf(ang) : cosf(ang);
        ov[j] = ev[j] * 32.0f + pe;
    }
    *(float4*)(X + (size_t)t * DEMB + d0) = make_float4(ov[0], ov[1], ov[2], ov[3]);
}

// ---------------- fused q/k/v per-head projection (grid.z selects) ----------------
__global__ __launch_bounds__(256) void proj_head3(
        const float* __restrict__ X0, const float* __restrict__ X1, const float* __restrict__ X2,
        const float* __restrict__ W0, const float* __restrict__ W1, const float* __restrict__ W2,
        float* __restrict__ O0, float* __restrict__ O1, float* __restrict__ O2) {
    const float* X; const float* W; float* O;
    if (blockIdx.z == 0)      { X = X0; W = W0; O = O0; }
    else if (blockIdx.z == 1) { X = X1; W = W1; O = O1; }
    else                      { X = X2; W = W2; O = O2; }
    __shared__ float Xs[64][64];
    __shared__ float Ws[64][64];
    int tid = threadIdx.x;
    int h = blockIdx.y;
    int t0 = blockIdx.x * 64;
#pragma unroll
    for (int r = 0; r < 4; r++) {
        int idx = tid + r * 256;
        int a = idx >> 4;
        int c4 = (idx & 15) << 2;
        float4 xv = *(const float4*)(X + (size_t)(t0 + a) * DEMB + h * DH + c4);
        Xs[c4 + 0][a] = xv.x; Xs[c4 + 1][a] = xv.y; Xs[c4 + 2][a] = xv.z; Xs[c4 + 3][a] = xv.w;
        float4 wv = *(const float4*)(W + a * DH + c4);
        *(float4*)&Ws[a][c4] = wv;
    }
    __syncthreads();
    int tx = tid & 15, ty = tid >> 4;
    float acc[4][4] = {};
#pragma unroll
    for (int d = 0; d < 64; d++) {
        float4 a4 = *(float4*)&Xs[d][ty * 4];
        float4 w4 = *(float4*)&Ws[d][tx * 4];
        float av[4] = {a4.x, a4.y, a4.z, a4.w};
        float wv[4] = {w4.x, w4.y, w4.z, w4.w};
#pragma unroll
        for (int i = 0; i < 4; i++)
#pragma unroll
            for (int j = 0; j < 4; j++) acc[i][j] = fmaf(av[i], wv[j], acc[i][j]);
    }
#pragma unroll
    for (int i = 0; i < 4; i++) {
        float4 o = make_float4(acc[i][0], acc[i][1], acc[i][2], acc[i][3]);
        *(float4*)(O + (size_t)(t0 + ty * 4 + i) * DEMB + h * DH + tx * 4) = o;
    }
}

// ---------------- residual add + layernorm: one warp per row, shuffle-only ----------------
__global__ __launch_bounds__(256) void add_ln(const float* __restrict__ A, const float* __restrict__ B,
                                              const float* __restrict__ g, const float* __restrict__ be,
                                              float* __restrict__ O) {
    int lane = threadIdx.x & 31, wid = threadIdx.x >> 5;
    int row = blockIdx.x * 8 + wid;
    size_t base = (size_t)row * DEMB;
    float4 v[8];
    float s1 = 0.0f, s2 = 0.0f;
#pragma unroll
    for (int p = 0; p < 8; p++) {
        float4 a = ((const float4*)(A + base))[lane + p * 32];
        float4 b = ((const float4*)(B + base))[lane + p * 32];
        float4 t = make_float4(a.x + b.x, a.y + b.y, a.z + b.z, a.w + b.w);
        v[p] = t;
        s1 += t.x + t.y + t.z + t.w;
        s2 += t.x * t.x + t.y * t.y + t.z * t.z + t.w * t.w;
    }
#pragma unroll
    for (int o = 16; o; o >>= 1) {
        s1 += __shfl_xor_sync(0xffffffffu, s1, o);
        s2 += __shfl_xor_sync(0xffffffffu, s2, o);
    }
    float mu = s1 * (1.0f / DEMB);
    float var = s2 * (1.0f / DEMB) - mu * mu;
    float w = rsqrtf(var + 1e-5f);
#pragma unroll
    for (int p = 0; p < 8; p++) {
        float4 gg = ((const float4*)g)[lane + p * 32];
        float4 bb = ((const float4*)be)[lane + p * 32];
        float4 t = v[p];
        float4 o;
        o.x = (t.x - mu) * w * gg.x + bb.x;
        o.y = (t.y - mu) * w * gg.y + bb.y;
        o.z = (t.z - mu) * w * gg.z + bb.z;
        o.w = (t.w - mu) * w * gg.w + bb.w;
        ((float4*)(O + base))[lane + p * 32] = o;
    }
}

// ---------------- host orchestration ----------------
extern "C" void kernel_launch(void* const* d_in, const int* in_sizes, int n_in,
                              void* d_out, int out_size) {
    const int*   ids   = (const int*)  d_in[0];
    const float* enc_k = (const float*)d_in[1];
    const float* enc_v = (const float*)d_in[2];
    const float* emb   = (const float*)d_in[3];
    const float* Wq_m  = (const float*)d_in[4];
    const float* Wk_m  = (const float*)d_in[5];
    const float* Wv_m  = (const float*)d_in[6];
    const float* Wq_c  = (const float*)d_in[7];
    const float* Wk_c  = (const float*)d_in[8];
    const float* Wv_c  = (const float*)d_in[9];
    const float* ln1_g = (const float*)d_in[10];
    const float* ln1_b = (const float*)d_in[11];
    const float* ln2_g = (const float*)d_in[12];
    const float* ln2_b = (const float*)d_in[13];
    const float* ln3_g = (const float*)d_in[14];
    const float* ln3_b = (const float*)d_in[15];
    const float* W1    = (const float*)d_in[16];
    const float* b1    = (const float*)d_in[17];
    const float* W2    = (const float*)d_in[18];
    const float* b2    = (const float*)d_in[19];
    const float* Wout  = (const float*)d_in[20];
    const float* bout  = (const float*)d_in[21];
    float* out = (float*)d_out;

    float *x, *h1, *h2, *t, *q, *k, *v, *ff;
    uint16_t *ah, *al, *bth, *btl;
    cudaGetSymbolAddress((void**)&x,  g_x);
    cudaGetSymbolAddress((void**)&h1, g_h1);
    cudaGetSymbolAddress((void**)&h2, g_h2);
    cudaGetSymbolAddress((void**)&t,  g_t);
    cudaGetSymbolAddress((void**)&q,  g_q);
    cudaGetSymbolAddress((void**)&k,  g_k);
    cudaGetSymbolAddress((void**)&v,  g_v);
    cudaGetSymbolAddress((void**)&ff, g_ff);
    cudaGetSymbolAddress((void**)&ah,  g_ah);
    cudaGetSymbolAddress((void**)&al,  g_al);
    cudaGetSymbolAddress((void**)&bth, g_bth);
    cudaGetSymbolAddress((void**)&btl, g_btl);

    cudaFuncSetAttribute(flash_attn, cudaFuncAttributeMaxDynamicSharedMemorySize, FA_SMEM_BYTES);
    cudaFuncSetAttribute(gemm_cp,   cudaFuncAttributeMaxDynamicSharedMemorySize, GEMM_SMEM);

    dim3 blk(256);
    dim3 projGrid(NTOK / 64, NHEAD, 3);
    dim3 faGrid(SEQ / 128, NB * NHEAD);
    dim3 tblk(256);

    embed_kernel<<<NTOK, blk>>>(ids, emb, x);

    for (int l = 0; l < NLAYER; l++) {
        size_t wOff  = (size_t)l * DH * DH;
        size_t lnOff = (size_t)l * DEMB;
        // --- masked self-attention ---
        proj_head3<<<projGrid, blk>>>(x, x, x, Wq_m + wOff, Wk_m + wOff, Wv_m + wOff, q, k, v);
        flash_attn<<<faGrid, blk, FA_SMEM_BYTES>>>(q, k, v, t, 1);
        add_ln<<<NTOK / 8, blk>>>(t, x, ln1_g + lnOff, ln1_b + lnOff, h1);
        // --- cross-attention ---
        proj_head3<<<projGrid, blk>>>(h1, enc_k, enc_v, Wq_c + wOff, Wk_c + wOff, Wv_c + wOff, q, k, v);
        flash_attn<<<faGrid, blk, FA_SMEM_BYTES>>>(q, k, v, t, 0);
        add_ln<<<NTOK / 8, blk>>>(t, h1, ln2_g + lnOff, ln2_b + lnOff, h2);
        // --- FFN (cp.async split-bf16 HMMA, 2 CTAs/SM) ---
        cvt_split<<<(NTOK * DEMB) / 1024, blk>>>(h2, ah, al);
        cvt_trans<<<dim3(DFF / 32, DEMB / 32), tblk>>>(W1 + (size_t)l * DEMB * DFF, bth, btl, DEMB, DFF);
        gemm_cp<<<dim3(NTOK / 128, DFF / 128), blk, GEMM_SMEM>>>(
            ah, al, bth, btl, b1 + (size_t)l * DFF, ff, DFF, DEMB, 1);
        cvt_split<<<(NTOK * DFF) / 1024, blk>>>(ff, ah, al);
        cvt_trans<<<dim3(DEMB / 32, DFF / 32), tblk>>>(W2 + (size_t)l * DFF * DEMB, bth, btl, DFF, DEMB);
        gemm_cp<<<dim3(NTOK / 128, DEMB / 128), blk, GEMM_SMEM>>>(
            ah, al, bth, btl, b2 + lnOff, t, DEMB, DFF, 0);
        add_ln<<<NTOK / 8, blk>>>(t, h2, ln3_g + lnOff, ln3_b + lnOff, x);
    }

    // --- vocab projection ---
    cvt_split<<<(NTOK * DEMB) / 1024, blk>>>(x, ah, al);
    cvt_trans<<<dim3(NVOCAB / 32, DEMB / 32), tblk>>>(Wout, bth, btl, DEMB, NVOCAB);
    gemm_cp<<<dim3(NTOK / 128, NVOCAB / 128), blk, GEMM_SMEM>>>(
        ah, al, bth, btl, bout, out, NVOCAB, DEMB, 0);
}